// round 2
// baseline (speedup 1.0000x reference)
#include <cuda_runtime.h>
#include <cstdint>

// One warp per edge: lane l loads h[src][4l..4l+3] and h[dst][4l..4l+3],
// computes a 4-wide partial dot, butterfly-reduces across the warp.
// Indices are int32 (JAX default x64-disabled downcasts int64 -> int32).
__global__ __launch_bounds__(256) void udotv_kernel(
    const float4* __restrict__ h,   // [N, 32] float4 view of [N,128] f32
    const int* __restrict__ src,    // [E] int32
    const int* __restrict__ dst,    // [E] int32
    float* __restrict__ out,        // [E]
    int n_edges)
{
    int warp_id = (blockIdx.x * blockDim.x + threadIdx.x) >> 5;
    int lane = threadIdx.x & 31;
    if (warp_id >= n_edges) return;

    int s = __ldg(&src[warp_id]);
    int d = __ldg(&dst[warp_id]);

    float4 a = __ldg(&h[(long long)s * 32 + lane]);
    float4 b = __ldg(&h[(long long)d * 32 + lane]);

    float sum = fmaf(a.x, b.x, fmaf(a.y, b.y, fmaf(a.z, b.z, a.w * b.w)));

    #pragma unroll
    for (int off = 16; off > 0; off >>= 1)
        sum += __shfl_xor_sync(0xffffffffu, sum, off);

    if (lane == 0) out[warp_id] = sum;
}

extern "C" void kernel_launch(void* const* d_in, const int* in_sizes, int n_in,
                              void* d_out, int out_size)
{
    const float4* h = (const float4*)d_in[0];
    const int* src = (const int*)d_in[1];
    const int* dst = (const int*)d_in[2];
    float* out = (float*)d_out;

    int n_edges = in_sizes[1];  // E = 640000
    int warps_per_block = 256 / 32;
    int blocks = (n_edges + warps_per_block - 1) / warps_per_block;
    udotv_kernel<<<blocks, 256>>>(h, src, dst, out, n_edges);
}

// round 3
// speedup vs baseline: 1.7231x; 1.7231x over previous
#include <cuda_runtime.h>
#include <cstdint>

// 4 edges per warp, 8 lanes per edge.
// Lane gl (0..7) of each group loads h[row][gl + 8k] (float4) for k=0..3,
// accumulates 16 FMAs locally, then 3-step butterfly reduce within the group.
// 8 independent LDG.128 per lane -> high MLP; shfl chain cut from 5 to 3.
__global__ __launch_bounds__(256) void udotv_kernel(
    const float4* __restrict__ h,   // [N, 32] float4 view of [N,128] f32
    const int* __restrict__ src,    // [E] int32
    const int* __restrict__ dst,    // [E] int32
    float* __restrict__ out,        // [E]
    int n_edges)
{
    int warp_id = (blockIdx.x * blockDim.x + threadIdx.x) >> 5;
    int lane = threadIdx.x & 31;
    int group = lane >> 3;          // 0..3: which edge in this warp
    int gl = lane & 7;              // lane within the 8-lane group

    long long e = (long long)warp_id * 4 + group;
    bool valid = (e < n_edges);
    long long ec = valid ? e : (n_edges - 1);   // clamp so all lanes stay in bounds

    int s = __ldg(&src[ec]);
    int d = __ldg(&dst[ec]);

    const float4* pa = h + (long long)s * 32 + gl;
    const float4* pb = h + (long long)d * 32 + gl;

    // 8 independent 16B loads, issued back-to-back (MLP = 8)
    float4 a0 = __ldg(pa);      float4 a1 = __ldg(pa + 8);
    float4 a2 = __ldg(pa + 16); float4 a3 = __ldg(pa + 24);
    float4 b0 = __ldg(pb);      float4 b1 = __ldg(pb + 8);
    float4 b2 = __ldg(pb + 16); float4 b3 = __ldg(pb + 24);

    // 4 independent accumulators -> short FMA dependency chains
    float s0 = fmaf(a0.x, b0.x, fmaf(a0.y, b0.y, fmaf(a0.z, b0.z, a0.w * b0.w)));
    float s1 = fmaf(a1.x, b1.x, fmaf(a1.y, b1.y, fmaf(a1.z, b1.z, a1.w * b1.w)));
    float s2 = fmaf(a2.x, b2.x, fmaf(a2.y, b2.y, fmaf(a2.z, b2.z, a2.w * b2.w)));
    float s3 = fmaf(a3.x, b3.x, fmaf(a3.y, b3.y, fmaf(a3.z, b3.z, a3.w * b3.w)));
    float sum = (s0 + s1) + (s2 + s3);

    // 3-step butterfly within each 8-lane group
    sum += __shfl_xor_sync(0xffffffffu, sum, 1);
    sum += __shfl_xor_sync(0xffffffffu, sum, 2);
    sum += __shfl_xor_sync(0xffffffffu, sum, 4);

    if (gl == 0 && valid) out[e] = sum;   // lanes 0,8,16,24: 4 consecutive floats
}

extern "C" void kernel_launch(void* const* d_in, const int* in_sizes, int n_in,
                              void* d_out, int out_size)
{
    const float4* h = (const float4*)d_in[0];
    const int* src = (const int*)d_in[1];
    const int* dst = (const int*)d_in[2];
    float* out = (float*)d_out;

    int n_edges = in_sizes[1];              // E = 640000
    int edges_per_block = 8 * 4;            // 8 warps x 4 edges
    int blocks = (n_edges + edges_per_block - 1) / edges_per_block;
    udotv_kernel<<<blocks, 256>>>(h, src, dst, out, n_edges);
}